// round 15
// baseline (speedup 1.0000x reference)
#include <cuda_runtime.h>

#define N_ATOMS  1024
#define NSLOTS   512            // 2-atom slots per batch
#define TPB      256
#define NSEG     16             // k-segments of 16 slot-steps (k = 1..256)
#define KSTEPS   16
#define TOTSLOTS 772            // 512 + dup tail (max slot touched = 769)
#define ZR_OFF   (TOTSLOTS * 16)   // byte offset of ZR array after XY array

__device__ float g_partials[2048];
__device__ unsigned int g_count = 0;

typedef unsigned long long u64;

__device__ __forceinline__ u64 fma2(u64 a, u64 b, u64 c) {
    u64 d; asm("fma.rn.f32x2 %0, %1, %2, %3;" : "=l"(d) : "l"(a), "l"(b), "l"(c)); return d;
}
__device__ __forceinline__ u64 add2(u64 a, u64 b) {
    u64 d; asm("add.rn.f32x2 %0, %1, %2;" : "=l"(d) : "l"(a), "l"(b)); return d;
}
__device__ __forceinline__ u64 mul2(u64 a, u64 b) {
    u64 d; asm("mul.rn.f32x2 %0, %1, %2;" : "=l"(d) : "l"(a), "l"(b)); return d;
}
__device__ __forceinline__ u64 pack2(float lo, float hi) {
    u64 d; asm("mov.b64 %0, {%1, %2};" : "=l"(d) : "f"(lo), "f"(hi)); return d;
}
__device__ __forceinline__ float fsqrt_approx(float x) {
    float r; asm("sqrt.approx.f32 %0, %1;" : "=f"(r) : "f"(x)); return r;
}

// load slot: XY line at 'off', ZR line at +ZR_OFF (immediate offset)
#define LOAD_SLOT(s, off) do {                                               \
    ulonglong2 _q1 = *(const ulonglong2*)(smem_c + (off));                   \
    ulonglong2 _q2 = *(const ulonglong2*)(smem_c + (off) + ZR_OFF);          \
    s##x = _q1.x; s##y = _q1.y; s##z = _q2.x; s##r = _q2.y;                  \
} while (0)

// 2 pairs: packed dot-chain, scalar sqrt+max tail (fmaxf is the NaN guard), packed acc
#define PAIR2(X, Y, Z, R, s, ACC) do {                                       \
    u64 _d2 = add2(fma2(X, s##x, fma2(Y, s##y, fma2(Z, s##z, s##r))), R);    \
    float _a, _b;                                                            \
    asm("mov.b64 {%0, %1}, %2;" : "=f"(_a), "=f"(_b) : "l"(_d2));            \
    float _v0 = fmaxf(2.9f - fsqrt_approx(_a), 0.0f);                        \
    float _v1 = fmaxf(2.9f - fsqrt_approx(_b), 0.0f);                        \
    u64 _V = pack2(_v0, _v1);                                                \
    ACC = fma2(_V, _V, ACC);                                                 \
} while (0)

// one slot-step: both rows vs buffer P (4 atom pairs), then refill P (1 IADD)
#define STEP(P) do {                                                         \
    PAIR2(X0, Y0, Z0, R0, P, acc0);                                          \
    PAIR2(X1, Y1, Z1, R1, P, acc1);                                          \
    LOAD_SLOT(P, off);                                                       \
    off += 16;                                                               \
} while (0)

__global__ void __launch_bounds__(TPB, 5)
collapse_kernel(const float* __restrict__ coords,
                float* __restrict__ out,
                int nblocks, float inv_b)
{
    // [0, ZR_OFF): XY lines (x0,x1,y0,y1); [ZR_OFF, 2*ZR_OFF): ZR lines (z0,z1,r0,r1)
    __shared__ float4 slab[2 * TOTSLOTS];       // 24.7 KB
    __shared__ float  wsum[TPB / 32];
    __shared__ bool   isLast;
    const char* smem_c = (const char*)slab;

    const int t    = threadIdx.x;
    const int bx   = blockIdx.x;                // 0..31
    const int half = bx & 1;
    const int kseg = bx >> 1;                   // 0..15
    const int b    = blockIdx.y;

    // ---- prologue: thread t loads atoms 4t..4t+3, builds slots 2t, 2t+1 ----
    {
        const float4* cb4 = (const float4*)(coords + (size_t)b * (3 * N_ATOMS));
        float4 f0 = cb4[3 * t + 0];
        float4 f1 = cb4[3 * t + 1];
        float4 f2 = cb4[3 * t + 2];
        float x0 = f0.x, y0 = f0.y, z0 = f0.z;
        float x1 = f0.w, y1 = f1.x, z1 = f1.y;
        float x2 = f1.z, y2 = f1.w, z2 = f2.x;
        float x3 = f2.y, y3 = f2.z, z3 = f2.w;
        // bake eps/2 into r so d2 = ri + rj - 2 dot carries the reference's +1e-8
        float r0 = fmaf(x0, x0, fmaf(y0, y0, z0 * z0)) + 5e-9f;
        float r1 = fmaf(x1, x1, fmaf(y1, y1, z1 * z1)) + 5e-9f;
        float r2 = fmaf(x2, x2, fmaf(y2, y2, z2 * z2)) + 5e-9f;
        float r3 = fmaf(x3, x3, fmaf(y3, y3, z3 * z3)) + 5e-9f;
        float4 xyA = make_float4(x0, x1, y0, y1);
        float4 zrA = make_float4(z0, z1, r0, r1);
        float4 xyB = make_float4(x2, x3, y2, y3);
        float4 zrB = make_float4(z2, z3, r2, r3);
        slab[2 * t]                 = xyA;
        slab[2 * t + 1]             = xyB;
        slab[TOTSLOTS + 2 * t]      = zrA;
        slab[TOTSLOTS + 2 * t + 1]  = zrB;
        if (t < 130) {                           // dup tail: slots 512..771 mirror 0..259
            slab[NSLOTS + 2 * t]                = xyA;
            slab[NSLOTS + 2 * t + 1]            = xyB;
            slab[TOTSLOTS + NSLOTS + 2 * t]     = zrA;
            slab[TOTSLOTS + NSLOTS + 2 * t + 1] = zrB;
        }
    }
    __syncthreads();

    // ---- this thread owns slot ci = 256*half + t (atoms 2ci, 2ci+1) ----
    const int ci = 256 * half + t;

    // ---- row constants from own slot (floats NOT kept live -> smaller reg set) ----
    u64 X0,Y0,Z0,R0, X1,Y1,Z1,R1;
    {
        float4 q1 = slab[ci];
        float4 q2 = slab[TOTSLOTS + ci];
        X0 = pack2(-2.f * q1.x, -2.f * q1.x);
        Y0 = pack2(-2.f * q1.z, -2.f * q1.z);
        Z0 = pack2(-2.f * q2.x, -2.f * q2.x);
        R0 = pack2(q2.z, q2.z);
        X1 = pack2(-2.f * q1.y, -2.f * q1.y);
        Y1 = pack2(-2.f * q1.w, -2.f * q1.w);
        Z1 = pack2(-2.f * q2.y, -2.f * q2.y);
        R1 = pack2(q2.w, q2.w);
    }

    // ---- prime 2-slot window at c0 = ci + 1 + 16*kseg ----
    const int c0 = ci + 1 + KSTEPS * kseg;
    u64 Ax,Ay,Az,Ar, Bx,By,Bz,Br;
    LOAD_SLOT(A, 16 * c0);
    LOAD_SLOT(B, 16 * (c0 + 1));
    int off = 16 * (c0 + 2);

    u64 acc0 = 0, acc1 = 0;

    // ---- main loop: 16 slot-steps, 2-slot ping-pong, fully unrolled ----
    #pragma unroll
    for (int it = 0; it < KSTEPS / 2; ++it) {
        STEP(A);
        STEP(B);
    }

    // ---- last kseg: slot-distance 256 counted by both partners -> subtract 0.5x ----
    if (kseg == NSEG - 1) {
        u64 Ex,Ey,Ez,Er;
        LOAD_SLOT(E, 16 * (ci + 256));
        const u64 NEGH = pack2(-0.5f, -0.5f);
        {
            u64 d2 = add2(fma2(X0, Ex, fma2(Y0, Ey, fma2(Z0, Ez, Er))), R0);
            float a, bb;
            asm("mov.b64 {%0, %1}, %2;" : "=f"(a), "=f"(bb) : "l"(d2));
            u64 V = pack2(fmaxf(2.9f - fsqrt_approx(a), 0.0f),
                          fmaxf(2.9f - fsqrt_approx(bb), 0.0f));
            acc0 = fma2(mul2(V, NEGH), V, acc0);
        }
        {
            u64 d2 = add2(fma2(X1, Ex, fma2(Y1, Ey, fma2(Z1, Ez, Er))), R1);
            float a, bb;
            asm("mov.b64 {%0, %1}, %2;" : "=f"(a), "=f"(bb) : "l"(d2));
            u64 V = pack2(fmaxf(2.9f - fsqrt_approx(a), 0.0f),
                          fmaxf(2.9f - fsqrt_approx(bb), 0.0f));
            acc1 = fma2(mul2(V, NEGH), V, acc1);
        }
    }

    // ---- unpack accumulators ----
    float a0f, a1f, a2f, a3f;
    asm("mov.b64 {%0, %1}, %2;" : "=f"(a0f), "=f"(a1f) : "l"(acc0));
    asm("mov.b64 {%0, %1}, %2;" : "=f"(a2f), "=f"(a3f) : "l"(acc1));
    float acc = (a0f + a1f) + (a2f + a3f);

    // ---- kseg0: intra-slot diagonal pair (2ci, 2ci+1); reload slot from slab ----
    if (kseg == 0) {
        float4 q1 = slab[ci];
        float4 q2 = slab[TOTSLOTS + ci];
        float dot = fmaf(q1.x, q1.y, fmaf(q1.z, q1.w, q2.x * q2.y));
        float d2  = fmaf(-2.f, dot, q2.z + q2.w);
        float v   = fmaxf(2.9f - fsqrt_approx(d2), 0.0f);
        acc = fmaf(v, v, acc);
    }

    // ---- intra-CTA reduction ----
    const int lane = t & 31, w = t >> 5;
    #pragma unroll
    for (int o = 16; o > 0; o >>= 1)
        acc += __shfl_down_sync(0xFFFFFFFFu, acc, o);
    if (lane == 0) wsum[w] = acc;
    __syncthreads();

    if (t == 0) {
        float s = 0.f;
        #pragma unroll
        for (int q = 0; q < TPB / 32; ++q) s += wsum[q];
        g_partials[blockIdx.y * gridDim.x + blockIdx.x] = s;
        __threadfence();
        unsigned int c = atomicAdd(&g_count, 1u);
        isLast = (c == (unsigned int)(nblocks - 1));
    }
    __syncthreads();

    // ---- last CTA: fixed-order deterministic final reduce ----
    if (isLast) {
        __threadfence();
        if (t < 32) {
            float s = 0.f;
            for (int k = t; k < nblocks; k += 32)
                s += g_partials[k];
            #pragma unroll
            for (int o = 16; o > 0; o >>= 1)
                s += __shfl_down_sync(0xFFFFFFFFu, s, o);
            if (t == 0) {
                out[0] = s * inv_b;
                g_count = 0;   // reset for graph replay
            }
        }
    }
}

extern "C" void kernel_launch(void* const* d_in, const int* in_sizes, int n_in,
                              void* d_out, int out_size)
{
    const float* coords = (const float*)d_in[0];
    const int B = in_sizes[0] / (3 * N_ATOMS);   // 64

    static bool configured = false;
    if (!configured) {
        cudaFuncSetAttribute(collapse_kernel,
                             cudaFuncAttributePreferredSharedMemoryCarveout, 100);
        configured = true;
    }

    dim3 grid(2 * NSEG, B);                      // (32, 64) = 2048 CTAs
    const int nblocks = 2 * NSEG * B;
    collapse_kernel<<<grid, TPB>>>(coords, (float*)d_out, nblocks, 1.0f / (float)B);
}

// round 16
// speedup vs baseline: 1.0184x; 1.0184x over previous
#include <cuda_runtime.h>

#define N_ATOMS 1024
#define B_MAX   64
#define NBUCK   256
#define INVWB   (256.0f / 48.0f)     // buckets of width 0.1875 over [-24, 24]
#define KWIN    17                   // window end = start of bucket (b + 17)

__device__ float4 g_sorted[B_MAX * N_ATOMS];   // (x, y, z, r+5e-9), sorted by x-bucket
__device__ int    g_endidx[B_MAX * N_ATOMS];   // per sorted atom: exclusive window end
__device__ float  g_partials[2048];
__device__ unsigned int g_count = 0;

__device__ __forceinline__ float fsqrt_approx(float x) {
    float r; asm("sqrt.approx.f32 %0, %1;" : "=f"(r) : "f"(x)); return r;
}

// ---------------- Phase 1: deterministic bucket sort by x ----------------
__global__ void __launch_bounds__(256)
sort_kernel(const float* __restrict__ coords)
{
    __shared__ float4 recs[N_ATOMS];            // 16 KB, original order
    __shared__ int    bkt[N_ATOMS];             // 4 KB
    __shared__ int    wcnt[NBUCK][8];           // 8 KB: per-bucket per-warp count -> prefix
    __shared__ unsigned short rankw[N_ATOMS];   // 2 KB: within-warp rank
    __shared__ int    tscan[NBUCK];             // 1 KB
    __shared__ int    bstart[NBUCK + 1];        // 1 KB

    const int t = threadIdx.x;
    const int b = blockIdx.x;                   // batch
    const int w = t >> 5, l = t & 31;

    // zero this warp's counter column (warp-local)
    for (int k = l; k < NBUCK; k += 32) wcnt[k][w] = 0;

    // load atoms 4t..4t+3, compute r (+eps/2 so pair d2 carries +1e-8) and bucket
    {
        const float4* cb4 = (const float4*)(coords + (size_t)b * (3 * N_ATOMS));
        float4 f0 = cb4[3 * t], f1 = cb4[3 * t + 1], f2 = cb4[3 * t + 2];
        float xs[4] = {f0.x, f0.w, f1.z, f2.y};
        float ys[4] = {f0.y, f1.x, f1.w, f2.z};
        float zs[4] = {f0.z, f1.y, f2.x, f2.w};
        #pragma unroll
        for (int c = 0; c < 4; ++c) {
            float r = fmaf(xs[c], xs[c], fmaf(ys[c], ys[c], zs[c] * zs[c])) + 5e-9f;
            recs[4 * t + c] = make_float4(xs[c], ys[c], zs[c], r);
            int bb = (int)((xs[c] + 24.0f) * INVWB);
            bkt[4 * t + c] = max(0, min(NBUCK - 1, bb));
        }
    }
    __syncwarp();

    // deterministic ranking: warp w ranks atoms [128w, 128w+128) in 4 lane-rounds
    #pragma unroll
    for (int r = 0; r < 4; ++r) {
        int a  = 128 * w + 32 * r + l;
        int bb = bkt[a];
        unsigned mask = __match_any_sync(0xFFFFFFFFu, bb);
        int myrank = __popc(mask & ((1u << l) - 1u));
        int base = wcnt[bb][w];
        __syncwarp();
        if (myrank == 0) wcnt[bb][w] = base + __popc(mask);   // group leader
        __syncwarp();
        rankw[a] = (unsigned short)(base + myrank);
    }
    __syncthreads();

    // per-bucket exclusive prefix over 8 warps; bucket totals into tscan
    {
        int run = 0;
        #pragma unroll
        for (int ww = 0; ww < 8; ++ww) { int c = wcnt[t][ww]; wcnt[t][ww] = run; run += c; }
        tscan[t] = run;
    }
    __syncthreads();

    // Hillis-Steele inclusive scan over 256 bucket totals
    for (int off = 1; off < NBUCK; off <<= 1) {
        int v = (t >= off) ? tscan[t - off] : 0;
        __syncthreads();
        tscan[t] += v;
        __syncthreads();
    }
    bstart[t + 1] = tscan[t];
    if (t == 0) bstart[0] = 0;
    __syncthreads();

    // scatter records + window-end indices to global (sorted order)
    {
        float4* gs = g_sorted + b * N_ATOMS;
        int*    ge = g_endidx + b * N_ATOMS;
        #pragma unroll
        for (int c = 0; c < 4; ++c) {
            int a   = 4 * t + c;
            int bb  = bkt[a];
            int pos = bstart[bb] + wcnt[bb][w] + rankw[a];
            gs[pos] = recs[a];
            ge[pos] = bstart[min(bb + KWIN, NBUCK)];
        }
    }
}

// ---------------- Phase 2: windowed pair scan ----------------
__global__ void __launch_bounds__(256)
pair_kernel(float* __restrict__ out, int nblocks, float inv_b)
{
    __shared__ float4 S[N_ATOMS];    // sorted batch, 16 KB
    __shared__ float  wsum[8];
    __shared__ bool   isLast;

    const int t  = threadIdx.x;
    const int cx = blockIdx.x;       // 0..15: atom chunk
    const int b  = blockIdx.y;       // batch

    // coalesced load of the whole sorted batch
    const float4* gs = g_sorted + b * N_ATOMS;
    #pragma unroll
    for (int k = 0; k < 4; ++k)
        S[t + 256 * k] = gs[t + 256 * k];
    __syncthreads();

    // 4 threads per atom: q splits the window into residues mod 4
    const int al = t >> 2;           // 0..63
    const int q  = t & 3;
    const int i  = 64 * cx + al;

    float4 ai = S[i];
    const float m2x = -2.f * ai.x, m2y = -2.f * ai.y, m2z = -2.f * ai.z, ri = ai.w;
    const int pend = g_endidx[b * N_ATOMS + i];

    float acc = 0.f;
    #pragma unroll 4
    for (int j = i + 1 + q; j < pend; j += 4) {
        float4 aj = S[j];
        float d2 = fmaf(m2x, aj.x, fmaf(m2y, aj.y, fmaf(m2z, aj.z, ri))) + aj.w;
        float v  = fmaxf(2.9f - fsqrt_approx(d2), 0.f);   // NaN guard: fmax(NaN,0)=0
        acc = fmaf(v, v, acc);
    }

    // intra-CTA reduction
    const int lane = t & 31, w = t >> 5;
    #pragma unroll
    for (int o = 16; o > 0; o >>= 1)
        acc += __shfl_down_sync(0xFFFFFFFFu, acc, o);
    if (lane == 0) wsum[w] = acc;
    __syncthreads();

    if (t == 0) {
        float s = 0.f;
        #pragma unroll
        for (int k = 0; k < 8; ++k) s += wsum[k];
        g_partials[b * gridDim.x + cx] = s;
        __threadfence();
        unsigned c = atomicAdd(&g_count, 1u);
        isLast = (c == (unsigned)(nblocks - 1));
    }
    __syncthreads();

    // last CTA: fixed-order deterministic final reduce
    if (isLast) {
        __threadfence();
        if (t < 32) {
            float s = 0.f;
            for (int k = t; k < nblocks; k += 32)
                s += g_partials[k];
            #pragma unroll
            for (int o = 16; o > 0; o >>= 1)
                s += __shfl_down_sync(0xFFFFFFFFu, s, o);
            if (t == 0) {
                out[0] = s * inv_b;
                g_count = 0;     // reset for graph replay
            }
        }
    }
}

extern "C" void kernel_launch(void* const* d_in, const int* in_sizes, int n_in,
                              void* d_out, int out_size)
{
    const float* coords = (const float*)d_in[0];
    const int B = in_sizes[0] / (3 * N_ATOMS);   // 64

    sort_kernel<<<B, 256>>>(coords);

    dim3 grid(16, B);                            // 1024 CTAs
    const int nblocks = 16 * B;
    pair_kernel<<<grid, 256>>>((float*)d_out, nblocks, 1.0f / (float)B);
}